// round 1
// baseline (speedup 1.0000x reference)
#include <cuda_runtime.h>
#include <cstdint>

// Problem constants
#define D      150       // true hidden dim
#define Dp     160       // padded hidden dim
#define NT     25600     // Dp*Dp (flattened (i,j))
#define BZ     256       // B*N = 2*128
#define DIN    1024
#define NTOK   128

// ---------------- scratch (static __device__ globals; zero-init at load) ----
__device__ float g_emb[3][BZ][Dp];          // 0=sh 1=st 2=p, cols >=150 stay 0
__device__ float g_Tt[6][Dp][NT];           // Tt[q][k][i*160+j] = T_q[i][k][j]
__device__ float g_w [6][BZ][NT];           // w[q][bz][i*160+j]
__device__ float g_v [6][BZ][NTOK * Dp];    // v[q][bz][x][j]

// operand selection per triaffine q:
// q0 span_psh: X=sh Y=st Z=p   q1 span_pst: X=sh Y=st Z=p
// q2 ph_sib:   X=sh Y=sh Z=p   q3 pt_sib:   X=st Y=st Z=p
// q4 ph_cop:   X=p  Y=p  Z=sh  q5 pt_cop:   X=p  Y=p  Z=st
__constant__ int c_ZI[6] = {2,2,2,2,0,1};
__constant__ int c_XI[6] = {0,0,0,1,2,2};
__constant__ int c_YI[6] = {1,1,0,1,2,2};

// ---------------- zero the buffers whose padding must be 0 -----------------
__global__ void k_zero()
{
    const size_t nTt  = (size_t)6 * Dp * NT;          // 24.576M floats
    const size_t nEmb = (size_t)3 * BZ * Dp;          // 122880 floats
    float* pT = &g_Tt[0][0][0];
    float* pE = &g_emb[0][0][0];
    size_t stride = (size_t)gridDim.x * blockDim.x;
    for (size_t i = blockIdx.x * (size_t)blockDim.x + threadIdx.x; i < nTt; i += stride)
        pT[i] = 0.f;
    for (size_t i = blockIdx.x * (size_t)blockDim.x + threadIdx.x; i < nEmb; i += stride)
        pE[i] = 0.f;
}

// ---------------- MLP: emb[e][row][c] = leaky(x[row]·W_e + b_e) ------------
__global__ void k_mlp(const float* __restrict__ x,
                      const float* __restrict__ W0, const float* __restrict__ b0,
                      const float* __restrict__ W1, const float* __restrict__ b1,
                      const float* __restrict__ W2, const float* __restrict__ b2)
{
    int row = blockIdx.x;      // 0..255 (= b*128 + token)
    int e   = blockIdx.y;      // 0..2
    const float* W = (e == 0) ? W0 : (e == 1) ? W1 : W2;
    const float* bb = (e == 0) ? b0 : (e == 1) ? b1 : b2;

    __shared__ float xs[DIN];
    int tid = threadIdx.x;     // 0..159
    for (int k = tid; k < DIN; k += 160) xs[k] = x[row * DIN + k];
    __syncthreads();

    if (tid < D) {
        float acc = bb[tid];
        #pragma unroll 8
        for (int k = 0; k < DIN; ++k)
            acc += xs[k] * W[k * D + tid];
        g_emb[e][row][tid] = (acc >= 0.f) ? acc : 0.1f * acc;
    }
}

// ---------------- transpose T[i,k,j] -> Tt[k][i*160+j] ---------------------
__global__ void k_transT(const float* __restrict__ T0, const float* __restrict__ T1,
                         const float* __restrict__ T2, const float* __restrict__ T3,
                         const float* __restrict__ T4, const float* __restrict__ T5)
{
    int k = blockIdx.x, i = blockIdx.y, q = blockIdx.z;
    const float* T = (q==0)?T0:(q==1)?T1:(q==2)?T2:(q==3)?T3:(q==4)?T4:T5;
    int j = threadIdx.x;
    if (j < D)
        g_Tt[q][k][i * Dp + j] = T[(i * D + k) * D + j];
}

// ---------------- stage A: w[q][bz][n] = sum_k Z[bz][k] * Tt[q][k][n] -------
// GEMM M=256 N=25600 K=160, tile 128x128xk32, 256 thr, 8x8 microtile
__global__ void __launch_bounds__(256, 2) k_stageA()
{
    int q  = blockIdx.z;
    int m0 = blockIdx.y * 128;
    int n0 = blockIdx.x * 128;
    const float* Zp = &g_emb[c_ZI[q]][0][0];   // [256][160]
    const float* Bp = &g_Tt[q][0][0];          // [160][25600]
    float*       Cp = &g_w[q][0][0];

    __shared__ float As[32][132];
    __shared__ float Bs[32][132];

    int tid = threadIdx.x;
    int ty = tid >> 4, tx = tid & 15;
    float acc[8][8];
    #pragma unroll
    for (int i = 0; i < 8; ++i)
        #pragma unroll
        for (int j = 0; j < 8; ++j) acc[i][j] = 0.f;

    for (int k0 = 0; k0 < Dp; k0 += 32) {
        {   // As[kc][m] = Z[m0+m][k0+kc]   (transposed load)
            int m = tid >> 1;
            int koff = (tid & 1) * 16;
            const float* src = Zp + (m0 + m) * Dp + k0 + koff;
            #pragma unroll
            for (int c = 0; c < 4; ++c) {
                float4 v = *(const float4*)(src + 4 * c);
                As[koff + 4*c + 0][m] = v.x;
                As[koff + 4*c + 1][m] = v.y;
                As[koff + 4*c + 2][m] = v.z;
                As[koff + 4*c + 3][m] = v.w;
            }
        }
        {   // Bs[kc][n] = Bp[(k0+kc)*NT + n0+n]  (direct, coalesced)
            int kc = tid >> 3;
            int noff = (tid & 7) * 16;
            const float* src = Bp + (size_t)(k0 + kc) * NT + n0 + noff;
            #pragma unroll
            for (int c = 0; c < 4; ++c)
                *(float4*)&Bs[kc][noff + 4*c] = *(const float4*)(src + 4*c);
        }
        __syncthreads();
        #pragma unroll
        for (int kc = 0; kc < 32; ++kc) {
            float4 a0 = *(const float4*)&As[kc][ty * 8];
            float4 a1 = *(const float4*)&As[kc][ty * 8 + 4];
            float4 b0 = *(const float4*)&Bs[kc][tx * 8];
            float4 b1 = *(const float4*)&Bs[kc][tx * 8 + 4];
            float a[8] = {a0.x,a0.y,a0.z,a0.w,a1.x,a1.y,a1.z,a1.w};
            float b[8] = {b0.x,b0.y,b0.z,b0.w,b1.x,b1.y,b1.z,b1.w};
            #pragma unroll
            for (int i = 0; i < 8; ++i)
                #pragma unroll
                for (int j = 0; j < 8; ++j)
                    acc[i][j] += a[i] * b[j];
        }
        __syncthreads();
    }
    #pragma unroll
    for (int i = 0; i < 8; ++i) {
        float* dst = Cp + (size_t)(m0 + ty * 8 + i) * NT + n0 + tx * 8;
        float4 s0 = {acc[i][0],acc[i][1],acc[i][2],acc[i][3]};
        float4 s1 = {acc[i][4],acc[i][5],acc[i][6],acc[i][7]};
        *(float4*)dst       = s0;
        *(float4*)(dst + 4) = s1;
    }
}

// ---------------- stage B: v[q][bz][x][j] = sum_i X[x][i] * w[i*160+j] -----
// GEMM per (q,bz): M=128 N=160 K=160, 256 thr, 8x10 microtile
__global__ void __launch_bounds__(256, 2) k_stageB()
{
    int q  = blockIdx.y;
    int bz = blockIdx.x;
    int b  = bz >> 7;
    const float* Xp = &g_emb[c_XI[q]][b * NTOK][0];  // [128][160]
    const float* Wp = &g_w[q][bz][0];                // [160][160]
    float*       Vp = &g_v[q][bz][0];                // [128][160]

    __shared__ float As[32][132];
    __shared__ float Bs[32][160];

    int tid = threadIdx.x;
    int ty = tid >> 4, tx = tid & 15;
    float acc[8][10];
    #pragma unroll
    for (int i = 0; i < 8; ++i)
        #pragma unroll
        for (int j = 0; j < 10; ++j) acc[i][j] = 0.f;

    for (int k0 = 0; k0 < Dp; k0 += 32) {
        {   // As[kc][m] = X[m][k0+kc]
            int m = tid >> 1;
            int koff = (tid & 1) * 16;
            const float* src = Xp + m * Dp + k0 + koff;
            #pragma unroll
            for (int c = 0; c < 4; ++c) {
                float4 v = *(const float4*)(src + 4 * c);
                As[koff + 4*c + 0][m] = v.x;
                As[koff + 4*c + 1][m] = v.y;
                As[koff + 4*c + 2][m] = v.z;
                As[koff + 4*c + 3][m] = v.w;
            }
        }
        {   // Bs[kc][j] = w[(k0+kc)*160 + j]
            int kc = tid >> 3;
            int joff = (tid & 7) * 20;
            const float* src = Wp + (k0 + kc) * Dp + joff;
            #pragma unroll
            for (int c = 0; c < 5; ++c)
                *(float4*)&Bs[kc][joff + 4*c] = *(const float4*)(src + 4*c);
        }
        __syncthreads();
        #pragma unroll
        for (int kc = 0; kc < 32; ++kc) {
            float4 a0 = *(const float4*)&As[kc][ty * 8];
            float4 a1 = *(const float4*)&As[kc][ty * 8 + 4];
            float a[8] = {a0.x,a0.y,a0.z,a0.w,a1.x,a1.y,a1.z,a1.w};
            float bb[10];
            #pragma unroll
            for (int c = 0; c < 5; ++c) {
                float2 v = *(const float2*)&Bs[kc][tx * 10 + 2 * c];
                bb[2*c] = v.x; bb[2*c+1] = v.y;
            }
            #pragma unroll
            for (int i = 0; i < 8; ++i)
                #pragma unroll
                for (int j = 0; j < 10; ++j)
                    acc[i][j] += a[i] * bb[j];
        }
        __syncthreads();
    }
    #pragma unroll
    for (int i = 0; i < 8; ++i) {
        float* dst = Vp + (ty * 8 + i) * Dp + tx * 10;
        #pragma unroll
        for (int c = 0; c < 5; ++c) {
            float2 s = {acc[i][2*c], acc[i][2*c+1]};
            *(float2*)(dst + 2 * c) = s;
        }
    }
}

// ---------------- stage C: s[x][y] = sum_j v[x][j] * Y[y][j]; sym + write ---
// GEMM per (q,bz): M=N=128 K=160; triu_sym fused via smem mirror exchange
__global__ void __launch_bounds__(256, 2) k_stageC(float* __restrict__ out)
{
    int q  = blockIdx.y;
    int bz = blockIdx.x;
    int b  = bz >> 7, z = bz & 127;
    const float* Ap = &g_v[q][bz][0];                // [128][160] (x, j)
    const float* Yp = &g_emb[c_YI[q]][b * NTOK][0];  // [128][160] (y, j)

    __shared__ float sm[2 * 32 * 132];               // 33792 B
    float (*As)[132] = (float (*)[132])sm;
    float (*Bs)[132] = (float (*)[132])(sm + 32 * 132);

    int tid = threadIdx.x;
    int ty = tid >> 4, tx = tid & 15;
    float acc[8][8];
    #pragma unroll
    for (int i = 0; i < 8; ++i)
        #pragma unroll
        for (int j = 0; j < 8; ++j) acc[i][j] = 0.f;

    for (int k0 = 0; k0 < Dp; k0 += 32) {
        {   // As[kc][x] = v[x][k0+kc]
            int m = tid >> 1;
            int koff = (tid & 1) * 16;
            const float* src = Ap + m * Dp + k0 + koff;
            #pragma unroll
            for (int c = 0; c < 4; ++c) {
                float4 v = *(const float4*)(src + 4 * c);
                As[koff + 4*c + 0][m] = v.x;
                As[koff + 4*c + 1][m] = v.y;
                As[koff + 4*c + 2][m] = v.z;
                As[koff + 4*c + 3][m] = v.w;
            }
        }
        {   // Bs[kc][y] = Y[y][k0+kc]
            int m = tid >> 1;
            int koff = (tid & 1) * 16;
            const float* src = Yp + m * Dp + k0 + koff;
            #pragma unroll
            for (int c = 0; c < 4; ++c) {
                float4 v = *(const float4*)(src + 4 * c);
                Bs[koff + 4*c + 0][m] = v.x;
                Bs[koff + 4*c + 1][m] = v.y;
                Bs[koff + 4*c + 2][m] = v.z;
                Bs[koff + 4*c + 3][m] = v.w;
            }
        }
        __syncthreads();
        #pragma unroll
        for (int kc = 0; kc < 32; ++kc) {
            float4 a0 = *(const float4*)&As[kc][ty * 8];
            float4 a1 = *(const float4*)&As[kc][ty * 8 + 4];
            float4 b0 = *(const float4*)&Bs[kc][tx * 8];
            float4 b1 = *(const float4*)&Bs[kc][tx * 8 + 4];
            float a[8] = {a0.x,a0.y,a0.z,a0.w,a1.x,a1.y,a1.z,a1.w};
            float bv[8] = {b0.x,b0.y,b0.z,b0.w,b1.x,b1.y,b1.z,b1.w};
            #pragma unroll
            for (int i = 0; i < 8; ++i)
                #pragma unroll
                for (int j = 0; j < 8; ++j)
                    acc[i][j] += a[i] * bv[j];
        }
        __syncthreads();
    }

    // Fused triu_sym: res[x][y] = (x<=y) ? s[x][y] : s[y][x]
    float res[8][8];
    if (q == 0) {
        #pragma unroll
        for (int i = 0; i < 8; ++i)
            #pragma unroll
            for (int j = 0; j < 8; ++j) res[i][j] = acc[i][j];
    } else {
        // upper-triangle threads (ty<tx) park tiles in (reused) smem
        if (ty < tx) {
            int u = ty * 15 - (ty * (ty - 1)) / 2 + (tx - ty - 1);   // 0..119
            #pragma unroll
            for (int i = 0; i < 8; ++i)
                #pragma unroll
                for (int j = 0; j < 8; ++j)
                    sm[u * 64 + i * 8 + j] = acc[i][j];
        }
        __syncthreads();
        if (ty < tx) {                      // strictly upper: keep own value
            #pragma unroll
            for (int i = 0; i < 8; ++i)
                #pragma unroll
                for (int j = 0; j < 8; ++j) res[i][j] = acc[i][j];
        } else if (ty == tx) {              // diagonal tile: local mirror
            #pragma unroll
            for (int i = 0; i < 8; ++i)
                #pragma unroll
                for (int j = 0; j < 8; ++j)
                    res[i][j] = (i <= j) ? acc[i][j] : acc[j][i];
        } else {                            // strictly lower: read mirror tile
            int u = tx * 15 - (tx * (tx - 1)) / 2 + (ty - tx - 1);
            #pragma unroll
            for (int i = 0; i < 8; ++i)
                #pragma unroll
                for (int j = 0; j < 8; ++j)
                    res[i][j] = sm[u * 64 + j * 8 + i];
        }
    }

    size_t qbase = (size_t)q * 4194304;     // 2*128^3 per output tensor
    if (q < 4) {
        // out[b][z][x][y]
        float* o = out + qbase + (size_t)bz * 16384;
        #pragma unroll
        for (int i = 0; i < 8; ++i) {
            float* dst = o + (ty * 8 + i) * 128 + tx * 8;
            float4 s0 = {res[i][0],res[i][1],res[i][2],res[i][3]};
            float4 s1 = {res[i][4],res[i][5],res[i][6],res[i][7]};
            *(float4*)dst       = s0;
            *(float4*)(dst + 4) = s1;
        }
    } else {
        // co-parent permute (0,2,3,1): out[b][x][y][z]
        float* o = out + qbase + (size_t)b * 2097152 + z;
        #pragma unroll
        for (int i = 0; i < 8; ++i)
            #pragma unroll
            for (int j = 0; j < 8; ++j)
                o[(size_t)(ty * 8 + i) * 16384 + (tx * 8 + j) * 128] = res[i][j];
    }
}

// ---------------------------------------------------------------------------
extern "C" void kernel_launch(void* const* d_in, const int* in_sizes, int n_in,
                              void* d_out, int out_size)
{
    const float* x      = (const float*)d_in[0];
    const float* W_sh   = (const float*)d_in[1];
    const float* b_sh   = (const float*)d_in[2];
    const float* W_st   = (const float*)d_in[3];
    const float* b_st   = (const float*)d_in[4];
    const float* W_p    = (const float*)d_in[5];
    const float* b_p    = (const float*)d_in[6];
    const float* T_pt   = (const float*)d_in[7];
    const float* T_ph   = (const float*)d_in[8];
    const float* T_phsib= (const float*)d_in[9];
    const float* T_ptsib= (const float*)d_in[10];
    const float* T_phcop= (const float*)d_in[11];
    const float* T_ptcop= (const float*)d_in[12];

    k_zero  <<<1024, 256>>>();
    k_mlp   <<<dim3(BZ, 3), 160>>>(x, W_sh, b_sh, W_st, b_st, W_p, b_p);
    // q order: 0=T_ph 1=T_pt 2=T_phsib 3=T_ptsib 4=T_phcop 5=T_ptcop
    k_transT<<<dim3(D, D, 6), 160>>>(T_ph, T_pt, T_phsib, T_ptsib, T_phcop, T_ptcop);
    k_stageA<<<dim3(200, 2, 6), 256>>>();
    k_stageB<<<dim3(BZ, 6), 256>>>();
    k_stageC<<<dim3(BZ, 6), 256>>>((float*)d_out);
}